// round 9
// baseline (speedup 1.0000x reference)
#include <cuda_runtime.h>
#include <math.h>
#include <stdint.h>

#define BSZ 16
#define NA  8400
#define NM  64
#define NC  80
#define KTOP 10
#define EPS9 1e-9f

#define NBX   16
#define NBINS 256          // 16x16 bins of 40px over 640x640
#define INV_BINW 0.025f    // 1/40
#define MAXC  1024

#define GRID  148          // one block per SM -> guaranteed co-resident
#define NTHR  512
#define NGT   (BSZ * NM)   // 1024
#define KBAR  5ULL
#define PER_LAUNCH (KBAR * (unsigned long long)GRID)   // 740

// ---------------- scratch (__device__ globals; allowed) ----------------
__device__ unsigned long long g_tick;     // barrier tick (multiple of 740 at entry)
__device__ int      g_hist[NBINS];        // zero at entry (initial + P1 re-zero)
__device__ int      g_ofs[NBINS];
__device__ int      g_bs[NBINS + 1];
__device__ float2   g_bxy[NA];
__device__ int      g_bidx[NA];
__device__ int      g_cnt[BSZ * NA];      // zero at entry (initial + P4 re-zero)
__device__ int      g_m[BSZ * NA];
__device__ float    g_al[BSZ * NA];
__device__ float    g_ov[BSZ * NA];
__device__ int      g_lbl[BSZ * NA];
__device__ int      g_tgt[BSZ * NA];
__device__ float    g_fin[BSZ * NA];
__device__ unsigned g_pos_al[NGT];
__device__ unsigned g_pos_ov[NGT];

// ---------------- helpers ----------------
static __device__ __forceinline__ float ciou_f(float4 g, float4 p) {
    const float eps = 1e-7f;
    float w1 = g.z - g.x, h1 = g.w - g.y;
    float w2 = p.z - p.x, h2 = p.w - p.y;
    float iw = fmaxf(fminf(g.z, p.z) - fmaxf(g.x, p.x), 0.0f);
    float ih = fmaxf(fminf(g.w, p.w) - fmaxf(g.y, p.y), 0.0f);
    float inter = iw * ih;
    float uni = w1 * h1 + w2 * h2 - inter + eps;
    float iou = inter / uni;
    float cw = fmaxf(g.z, p.z) - fminf(g.x, p.x);
    float ch = fmaxf(g.w, p.w) - fminf(g.y, p.y);
    float c2 = cw * cw + ch * ch + eps;
    float dx = p.x + p.z - g.x - g.z;
    float dy = p.y + p.w - g.y - g.w;
    float rho2 = (dx * dx + dy * dy) * 0.25f;
    float d = atanf(w1 / (h1 + eps)) - atanf(w2 / (h2 + eps));
    float v = 0.4052847345693511f * d * d;   // 4/pi^2
    float alpha = v / (v - iou + 1.0f + eps);
    return iou - (rho2 / c2 + v * alpha);
}

static __device__ __forceinline__ bool inside_box(float2 a, float4 g) {
    float m0 = fminf(a.x - g.x, a.y - g.y);
    float m1 = fminf(g.z - a.x, g.w - a.y);
    return fminf(m0, m1) > EPS9;
}

static __device__ __forceinline__ int bin_of(float2 an) {
    int bx = min(max((int)(an.x * INV_BINW), 0), NBX - 1);
    int by = min(max((int)(an.y * INV_BINW), 0), NBX - 1);
    return by * NBX + bx;
}

// grid-wide barrier: monotonic tick, goal = base + i*GRID
static __device__ __forceinline__ void grid_barrier(unsigned long long goal) {
    __syncthreads();
    __threadfence();
    if (threadIdx.x == 0) {
        atomicAdd(&g_tick, 1ULL);
        while (atomicAdd(&g_tick, 0ULL) < goal) __nanosleep(128);
        __threadfence();
    }
    __syncthreads();
}

// ---------------- the fused kernel ----------------
__global__ void __launch_bounds__(NTHR, 1) k_fused(
    const float* __restrict__ pd_scores, const float* __restrict__ pd_bboxes,
    const float* __restrict__ anc, const int* __restrict__ gt_labels,
    const float* __restrict__ gt_bboxes, float* __restrict__ out)
{
    int tid = threadIdx.x;
    int bid = blockIdx.x;

    __shared__ __align__(16) unsigned char s_raw[MAXC * 16];   // 16 KB, phase-aliased
    __shared__ unsigned long long s_base;
    __shared__ int s_n;

    if (tid == 0)
        s_base = (atomicAdd(&g_tick, 0ULL) / PER_LAUNCH) * PER_LAUNCH;
    __syncthreads();
    unsigned long long base = s_base;

    // ---- P0: zero pos arrays + global bin histogram ----
    for (int i = bid * NTHR + tid; i < NGT; i += GRID * NTHR) {
        g_pos_al[i] = 0u; g_pos_ov[i] = 0u;
    }
    for (int a = bid * NTHR + tid; a < NA; a += GRID * NTHR) {
        float2 an = __ldg((const float2*)anc + a);
        atomicAdd(&g_hist[bin_of(an)], 1);
    }
    grid_barrier(base + 1 * GRID);

    // ---- P1: block0 scans histogram -> g_bs, g_ofs; re-zero g_hist ----
    if (bid == 0) {
        int* h   = (int*)s_raw;
        int* scn = h + NBINS;
        if (tid < NBINS) { int v = __ldcg(&g_hist[tid]); h[tid] = v; scn[tid] = v; }
        __syncthreads();
        for (int d = 1; d < NBINS; d <<= 1) {
            int v = (tid < NBINS && tid >= d) ? scn[tid - d] : 0;
            __syncthreads();
            if (tid < NBINS) scn[tid] += v;
            __syncthreads();
        }
        if (tid < NBINS) {
            int excl = scn[tid] - h[tid];
            __stcg(&g_bs[tid], excl);
            __stcg(&g_ofs[tid], excl);
            __stcg(&g_hist[tid], 0);
        }
        if (tid == 0) __stcg(&g_bs[NBINS], NA);
    }
    grid_barrier(base + 2 * GRID);

    // ---- P2: scatter anchors into bins ----
    for (int a = bid * NTHR + tid; a < NA; a += GRID * NTHR) {
        float2 an = __ldg((const float2*)anc + a);
        int p = atomicAdd(&g_ofs[bin_of(an)], 1);
        __stcg(&g_bxy[p], an);
        __stcg(&g_bidx[p], a);
    }
    grid_barrier(base + 3 * GRID);

    // ---- P3: per-gt binned scan + parallel rank top-10 ----
    {
        unsigned long long* s_key = (unsigned long long*)s_raw;
        float* s_ovs = (float*)(s_raw + 8 * MAXC);
        int*   s_ia  = (int*)(s_raw + 12 * MAXC);

        for (int bm = bid; bm < NGT; bm += GRID) {
            if (tid == 0) s_n = 0;
            int b = bm >> 6;
            float4 g = __ldg((const float4*)gt_bboxes + bm);
            int lbl = __ldg(gt_labels + bm);
            const float* sc = pd_scores + (size_t)b * NA * NC + lbl;
            const float4* pb = (const float4*)pd_bboxes + (size_t)b * NA;
            __syncthreads();

            int bx0 = min(max((int)(g.x * INV_BINW), 0), NBX - 1);
            int bx1 = min(max((int)(g.z * INV_BINW), 0), NBX - 1);
            int by0 = min(max((int)(g.y * INV_BINW), 0), NBX - 1);
            int by1 = min(max((int)(g.w * INV_BINW), 0), NBX - 1);

            for (int by = by0; by <= by1; by++) {
                int j0 = __ldcg(&g_bs[by * NBX + bx0]);
                int j1 = __ldcg(&g_bs[by * NBX + bx1 + 1]);
                for (int j = j0 + tid; j < j1; j += NTHR) {
                    float2 an = __ldcg(&g_bxy[j]);
                    if (!inside_box(an, g)) continue;
                    int a = __ldcg(&g_bidx[j]);
                    float4 p = __ldg(pb + a);
                    float ov = fmaxf(ciou_f(g, p), 0.0f);
                    if (ov <= 0.0f) continue;
                    float s = __ldg(sc + (size_t)a * NC);
                    float o2 = ov * ov;
                    float v = sqrtf(s) * o2 * o2 * o2;   // > 0
                    int pos = atomicAdd(&s_n, 1);
                    if (pos < MAXC) {
                        s_key[pos] = ((unsigned long long)__float_as_uint(v) << 32) |
                                     (unsigned)(0x7FFFFFFF - a);
                        s_ovs[pos] = ov;
                        s_ia[pos]  = a;
                    }
                }
            }
            __syncthreads();

            int n = min(s_n, MAXC);

            // parallel rank-select: distinct keys, winner iff rank < KTOP
            for (int c = tid; c < n; c += NTHR) {
                unsigned long long key = s_key[c];
                int rank = 0;
                for (int j = 0; j < n; j++) rank += (s_key[j] > key);
                if (rank < KTOP) {
                    int a = s_ia[c];
                    size_t i = (size_t)b * NA + a;
                    atomicAdd(&g_cnt[i], 1);
                    __stcg(&g_m[i], bm & 63);
                    __stcg(&g_al[i], __uint_as_float((unsigned)(key >> 32)));
                    __stcg(&g_ov[i], s_ovs[c]);
                }
            }

            // fillers when n < KTOP: smallest global anchor indices not positive
            if (n < KTOP && tid < n + KTOP) {
                bool inPos = false; int less = 0;
                for (int j = 0; j < n; j++) {
                    int ia = s_ia[j];
                    inPos |= (ia == tid);
                    less  += (ia < tid);
                }
                if (!inPos && (tid - less) < (KTOP - n)) {
                    float2 an = __ldg((const float2*)anc + tid);
                    if (inside_box(an, g)) {
                        size_t i = (size_t)b * NA + tid;
                        atomicAdd(&g_cnt[i], 1);
                        __stcg(&g_m[i], bm & 63);
                        __stcg(&g_al[i], 0.0f);
                        float4 p = __ldg(pb + tid);
                        __stcg(&g_ov[i], fmaxf(ciou_f(g, p), 0.0f));
                    }
                }
            }
            __syncthreads();   // before s_n/s_key reuse
        }
    }
    grid_barrier(base + 4 * GRID);

    // ---- P4: resolve assignment + pos-max atomics; self-zero g_cnt ----
    for (int idx = bid * NTHR + tid; idx < BSZ * NA; idx += GRID * NTHR) {
        size_t i = (size_t)idx;
        int b = idx / NA;
        int a = idx - b * NA;

        int   cnt = __ldcg(&g_cnt[i]);
        int   tgt = __ldcg(&g_m[i]);
        float al  = __ldcg(&g_al[i]);
        float ov  = __ldcg(&g_ov[i]);
        __stcg(&g_cnt[i], 0);                 // clean for next launch

        if (cnt == 0) {
            __stcg(&g_lbl[i], -1); __stcg(&g_tgt[i], 0); __stcg(&g_fin[i], 0.0f);
            continue;
        }

        if (cnt > 1) {
            float2 an = __ldg((const float2*)anc + a);
            float4 p  = __ldg((const float4*)pd_bboxes + (size_t)b * NA + a);
            const float4* gb = (const float4*)gt_bboxes + b * NM;
            float best = -1.0f; int bmx = 0;
#pragma unroll 4
            for (int m = 0; m < NM; m++) {
                float4 gg = __ldg(gb + m);
                float ovm = inside_box(an, gg) ? fmaxf(ciou_f(gg, p), 0.0f) : 0.0f;
                if (ovm > best) { best = ovm; bmx = m; }
            }
            tgt = bmx; ov = best;
            float4 gg = __ldg(gb + tgt);
            if (inside_box(an, gg) && ov > 0.0f) {
                int lb = __ldg(gt_labels + b * NM + tgt);
                float s = pd_scores[(size_t)b * NA * NC + (size_t)a * NC + lb];
                float o2 = ov * ov;
                al = sqrtf(s) * o2 * o2 * o2;
            } else {
                al = 0.0f;
            }
        }

        __stcg(&g_lbl[i], __ldg(gt_labels + b * NM + tgt));
        __stcg(&g_tgt[i], tgt);
        __stcg(&g_fin[i], al);
        atomicMax(&g_pos_al[b * NM + tgt], __float_as_uint(al));
        atomicMax(&g_pos_ov[b * NM + tgt], __float_as_uint(ov));
    }
    grid_barrier(base + 5 * GRID);

    // ---- P5: all outputs (tiles of 128 anchors, dense coalesced scores) ----
    {
        float* s_norm = (float*)s_raw;
        int*   s_lbl  = (int*)(s_raw + 128 * sizeof(float));
        const size_t N = (size_t)BSZ * NA;
        const int TPI = 66;                    // tiles per image (66*128 >= 8400)
        const int TILES = BSZ * TPI;

        for (int t = bid; t < TILES; t += GRID) {
            int b  = t / TPI;
            int a0 = (t - b * TPI) * 128;
            __syncthreads();                   // protect shared reuse

            if (tid < 128) {
                int a = a0 + tid;
                float norm = 0.0f; int lbl = -1;
                if (a < NA) {
                    size_t i = (size_t)b * NA + a;
                    lbl     = __ldcg(&g_lbl[i]);
                    int tgt = __ldcg(&g_tgt[i]);
                    int fg  = lbl >= 0;

                    float4 box = __ldg((const float4*)gt_bboxes + b * NM + tgt);
                    out[i] = fg ? (float)lbl : (float)NC;                 // labels
                    ((float4*)(out + N))[i] = box;                        // bboxes
                    out[N * (size_t)85 + i] = fg ? 1.0f : 0.0f;           // fg
                    out[N * (size_t)86 + i] = (float)tgt;                 // gt_idx

                    if (fg) {
                        float pa = __uint_as_float(__ldcg(&g_pos_al[b * NM + tgt]));
                        float po = __uint_as_float(__ldcg(&g_pos_ov[b * NM + tgt]));
                        norm = __ldcg(&g_fin[i]) * po / (pa + EPS9);
                    }
                }
                s_norm[tid] = norm; s_lbl[tid] = lbl;
            }
            __syncthreads();

            float4* basep = (float4*)(out + N * 5) + ((size_t)b * NA + a0) * (NC / 4);
#pragma unroll
            for (int r = 0; r < (128 * NC / 4) / NTHR; r++) {   // 5 iterations
                int idx = r * NTHR + tid;
                int al  = idx / (NC / 4);
                int k   = idx - al * (NC / 4);
                if (a0 + al < NA) {
                    int lbl = s_lbl[al];
                    float4 w = make_float4(0.f, 0.f, 0.f, 0.f);
                    if ((lbl >> 2) == k) {
                        float nv = s_norm[al];
                        int l4 = lbl & 3;
                        if      (l4 == 0) w.x = nv;
                        else if (l4 == 1) w.y = nv;
                        else if (l4 == 2) w.z = nv;
                        else              w.w = nv;
                    }
                    basep[idx] = w;
                }
            }
        }
    }
}

// ---------------- launcher ----------------
extern "C" void kernel_launch(void* const* d_in, const int* in_sizes, int n_in,
                              void* d_out, int out_size)
{
    const float* pd_scores = (const float*)d_in[0];
    const float* pd_bboxes = (const float*)d_in[1];
    const float* anc       = (const float*)d_in[2];
    const int*   gt_labels = (const int*)  d_in[3];
    const float* gt_bboxes = (const float*)d_in[4];
    float* out = (float*)d_out;

    (void)in_sizes; (void)n_in; (void)out_size;

    k_fused<<<GRID, NTHR>>>(pd_scores, pd_bboxes, anc, gt_labels, gt_bboxes, out);
}

// round 10
// speedup vs baseline: 1.6960x; 1.6960x over previous
#include <cuda_runtime.h>
#include <math.h>
#include <stdint.h>

#define BSZ 16
#define NA  8400
#define NM  64
#define NC  80
#define KTOP 10
#define EPS9 1e-9f

#define NBX   16
#define NBINS 256          // 16x16 bins of 40px over 640x640
#define INV_BINW 0.025f    // 1/40
#define MAXC  1024

// ---------------- scratch (__device__ globals; zero-initialized) ----------
__device__ int      g_cnt[BSZ * NA];     // zero at entry (initial + phaseB clean)
__device__ int      g_m[BSZ * NA];
__device__ float    g_al[BSZ * NA];
__device__ float    g_ov[BSZ * NA];
__device__ int      g_lbl[BSZ * NA];     // final label, -1 = background
__device__ int      g_tgt[BSZ * NA];
__device__ float    g_fin[BSZ * NA];
__device__ unsigned g_pos_al[BSZ * NM];  // zeroed by phaseA block bm each launch
__device__ unsigned g_pos_ov[BSZ * NM];
// binning
__device__ float2   g_bxy[NA];
__device__ int      g_bidx[NA];
__device__ int      g_bs[NBINS + 1];

// ---------------- helpers ----------------
static __device__ __forceinline__ float ciou_f(float4 g, float4 p) {
    const float eps = 1e-7f;
    float w1 = g.z - g.x, h1 = g.w - g.y;
    float w2 = p.z - p.x, h2 = p.w - p.y;
    float iw = fmaxf(fminf(g.z, p.z) - fmaxf(g.x, p.x), 0.0f);
    float ih = fmaxf(fminf(g.w, p.w) - fmaxf(g.y, p.y), 0.0f);
    float inter = iw * ih;
    float uni = w1 * h1 + w2 * h2 - inter + eps;
    float iou = inter / uni;
    float cw = fmaxf(g.z, p.z) - fminf(g.x, p.x);
    float ch = fmaxf(g.w, p.w) - fminf(g.y, p.y);
    float c2 = cw * cw + ch * ch + eps;
    float dx = p.x + p.z - g.x - g.z;
    float dy = p.y + p.w - g.y - g.w;
    float rho2 = (dx * dx + dy * dy) * 0.25f;
    float d = atanf(w1 / (h1 + eps)) - atanf(w2 / (h2 + eps));
    float v = 0.4052847345693511f * d * d;   // 4/pi^2
    float alpha = v / (v - iou + 1.0f + eps);
    return iou - (rho2 / c2 + v * alpha);
}

static __device__ __forceinline__ bool inside_box(float2 a, float4 g) {
    float m0 = fminf(a.x - g.x, a.y - g.y);
    float m1 = fminf(g.z - a.x, g.w - a.y);
    return fminf(m0, m1) > EPS9;
}

static __device__ __forceinline__ int bin_of(float2 an) {
    int bx = min(max((int)(an.x * INV_BINW), 0), NBX - 1);
    int by = min(max((int)(an.y * INV_BINW), 0), NBX - 1);
    return by * NBX + bx;
}

// ---------------- K0: bin anchors (single block, 1024 threads) -----------
__global__ void __launch_bounds__(1024) k_bin(const float* __restrict__ anc) {
    __shared__ int cnt[NBINS];
    __shared__ int ofs[NBINS];
    __shared__ int scn[NBINS];
    int tid = threadIdx.x;
    if (tid < NBINS) cnt[tid] = 0;
    __syncthreads();
    for (int a = tid; a < NA; a += 1024) {
        float2 an = __ldg((const float2*)anc + a);
        atomicAdd(&cnt[bin_of(an)], 1);
    }
    __syncthreads();
    if (tid < NBINS) scn[tid] = cnt[tid];
    __syncthreads();
#pragma unroll
    for (int d = 1; d < NBINS; d <<= 1) {
        int v = (tid < NBINS && tid >= d) ? scn[tid - d] : 0;
        __syncthreads();
        if (tid < NBINS) scn[tid] += v;
        __syncthreads();
    }
    if (tid < NBINS) {
        int excl = scn[tid] - cnt[tid];
        g_bs[tid] = excl;
        ofs[tid]  = excl;
    }
    if (tid == 0) g_bs[NBINS] = NA;
    __syncthreads();
    for (int a = tid; a < NA; a += 1024) {
        float2 an = __ldg((const float2*)anc + a);
        int p = atomicAdd(&ofs[bin_of(an)], 1);
        g_bxy[p]  = an;
        g_bidx[p] = a;
    }
}

// ---------------- K1: per (b,m) binned scan + parallel rank top-10 --------
__global__ void __launch_bounds__(128) k_phaseA(
    const float* __restrict__ pd_scores, const float* __restrict__ pd_bboxes,
    const float* __restrict__ anc, const int* __restrict__ gt_labels,
    const float* __restrict__ gt_bboxes)
{
    int bm = blockIdx.x;
    int b = bm >> 6;
    int tid = threadIdx.x;

    __shared__ unsigned long long s_key[MAXC];  // (vbits<<32)|(0x7FFFFFFF - idx)
    __shared__ float s_ovs[MAXC];
    __shared__ int   s_ia[MAXC];
    __shared__ int   s_n;
    if (tid == 0) {
        s_n = 0;
        g_pos_al[bm] = 0u;          // safe: prior replay's phaseC already read
        g_pos_ov[bm] = 0u;
    }

    float4 g = __ldg((const float4*)gt_bboxes + bm);
    int lbl = __ldg(gt_labels + bm);
    const float* sc = pd_scores + (size_t)b * NA * NC + lbl;
    const float4* pb = (const float4*)pd_bboxes + (size_t)b * NA;
    __syncthreads();

    int bx0 = min(max((int)(g.x * INV_BINW), 0), NBX - 1);
    int bx1 = min(max((int)(g.z * INV_BINW), 0), NBX - 1);
    int by0 = min(max((int)(g.y * INV_BINW), 0), NBX - 1);
    int by1 = min(max((int)(g.w * INV_BINW), 0), NBX - 1);

    for (int by = by0; by <= by1; by++) {
        int j0 = g_bs[by * NBX + bx0];
        int j1 = g_bs[by * NBX + bx1 + 1];
        for (int j = j0 + tid; j < j1; j += 128) {
            float2 an = g_bxy[j];
            if (!inside_box(an, g)) continue;
            int a = g_bidx[j];
            float4 p = __ldg(pb + a);
            float ov = fmaxf(ciou_f(g, p), 0.0f);
            if (ov <= 0.0f) continue;
            float s = __ldg(sc + (size_t)a * NC);
            float o2 = ov * ov;
            float v = sqrtf(s) * o2 * o2 * o2;   // > 0
            int pos = atomicAdd(&s_n, 1);
            if (pos < MAXC) {
                s_key[pos] = ((unsigned long long)__float_as_uint(v) << 32) |
                             (unsigned)(0x7FFFFFFF - a);
                s_ovs[pos] = ov;
                s_ia[pos]  = a;
            }
        }
    }
    __syncthreads();

    int n = min(s_n, MAXC);

    // parallel rank-select: keys distinct, winner iff rank < KTOP
    for (int c = tid; c < n; c += 128) {
        unsigned long long key = s_key[c];
        int rank = 0;
        for (int j = 0; j < n; j++) rank += (s_key[j] > key);
        if (rank < KTOP) {
            int a = s_ia[c];
            size_t i = (size_t)b * NA + a;
            atomicAdd(&g_cnt[i], 1);
            g_m[i]  = bm & 63;
            g_al[i] = __uint_as_float((unsigned)(key >> 32));
            g_ov[i] = s_ovs[c];
        }
    }

    // fillers when n < KTOP: smallest global anchor indices not positive
    if (n < KTOP && tid < n + KTOP) {
        bool inPos = false; int less = 0;
        for (int j = 0; j < n; j++) {
            int ia = s_ia[j];
            inPos |= (ia == tid);
            less  += (ia < tid);
        }
        if (!inPos && (tid - less) < (KTOP - n)) {
            float2 an = __ldg((const float2*)anc + tid);
            if (inside_box(an, g)) {
                size_t i = (size_t)b * NA + tid;
                atomicAdd(&g_cnt[i], 1);
                g_m[i]  = bm & 63;
                g_al[i] = 0.0f;
                float4 p = __ldg(pb + tid);
                g_ov[i] = fmaxf(ciou_f(g, p), 0.0f);
            }
        }
    }
}

// ---------------- K2: resolve assignment (2 anchors/thread) ---------------
__global__ void __launch_bounds__(256) k_phaseB(
    const float* __restrict__ pd_scores, const float* __restrict__ pd_bboxes,
    const float* __restrict__ anc, const int* __restrict__ gt_labels,
    const float* __restrict__ gt_bboxes)
{
    int b = blockIdx.y;
    int a_base = blockIdx.x * 512 + threadIdx.x;

    int   aa[2];
    int   cnt[2], tgt[2];
    float al[2], ov[2];

    // upfront independent loads for both anchors
#pragma unroll
    for (int u = 0; u < 2; u++) {
        int a = a_base + u * 256;
        aa[u] = a;
        if (a < NA) {
            size_t i = (size_t)b * NA + a;
            cnt[u] = __ldg(&g_cnt[i]);
            tgt[u] = __ldg(&g_m[i]);
            al[u]  = __ldg(&g_al[i]);
            ov[u]  = __ldg(&g_ov[i]);
        } else cnt[u] = -1;
    }

#pragma unroll
    for (int u = 0; u < 2; u++) {
        int a = aa[u];
        if (cnt[u] < 0) continue;
        size_t i = (size_t)b * NA + a;
        g_cnt[i] = 0;                       // self-clean for next launch

        if (cnt[u] == 0) {
            g_lbl[i] = -1; g_tgt[i] = 0; g_fin[i] = 0.0f;
            continue;
        }

        int   t  = tgt[u];
        float av = al[u], ovv = ov[u];

        if (cnt[u] > 1) {
            // multi-assigned: argmax over m of overlaps (ties -> lowest m)
            float2 an = __ldg((const float2*)anc + a);
            float4 p  = __ldg((const float4*)pd_bboxes + (size_t)b * NA + a);
            const float4* gb = (const float4*)gt_bboxes + b * NM;
            float best = -1.0f; int bmx = 0;
#pragma unroll 4
            for (int m = 0; m < NM; m++) {
                float4 gg = __ldg(gb + m);
                float ovm = inside_box(an, gg) ? fmaxf(ciou_f(gg, p), 0.0f) : 0.0f;
                if (ovm > best) { best = ovm; bmx = m; }
            }
            t = bmx; ovv = best;
            float4 gg = __ldg(gb + t);
            if (inside_box(an, gg) && ovv > 0.0f) {
                int lb = __ldg(gt_labels + b * NM + t);
                float s = pd_scores[(size_t)b * NA * NC + (size_t)a * NC + lb];
                float o2 = ovv * ovv;
                av = sqrtf(s) * o2 * o2 * o2;
            } else {
                av = 0.0f;
            }
        }

        g_lbl[i] = __ldg(gt_labels + b * NM + t);
        g_tgt[i] = t;
        g_fin[i] = av;
        atomicMax(&g_pos_al[b * NM + t], __float_as_uint(av));
        atomicMax(&g_pos_ov[b * NM + t], __float_as_uint(ovv));
    }
}

// ---------------- K3: all outputs (warp-autonomous, shfl exchange) --------
__global__ void __launch_bounds__(256) k_phaseC(
    const float* __restrict__ gt_bboxes, float* __restrict__ out)
{
    int b    = blockIdx.y;
    int lane = threadIdx.x & 31;
    int w    = threadIdx.x >> 5;
    int arow = blockIdx.x * 64 + w * 8;      // this warp's 8 anchors

    const size_t N = (size_t)BSZ * NA;

    float norm = 0.0f; int lbl = -1;
    int a = arow + lane;
    if (lane < 8 && a < NA) {
        size_t i = (size_t)b * NA + a;
        lbl     = __ldg(&g_lbl[i]);
        int tgt = __ldg(&g_tgt[i]);
        int fg  = lbl >= 0;

        float4 box = __ldg((const float4*)gt_bboxes + b * NM + tgt);
        out[i] = fg ? (float)lbl : (float)NC;               // labels
        ((float4*)(out + N))[i] = box;                      // bboxes
        out[N * (size_t)85 + i] = fg ? 1.0f : 0.0f;         // fg
        out[N * (size_t)86 + i] = (float)tgt;               // gt_idx

        if (fg) {
            float pa = __uint_as_float(__ldg(&g_pos_al[b * NM + tgt]));
            float po = __uint_as_float(__ldg(&g_pos_ov[b * NM + tgt]));
            norm = __ldg(&g_fin[i]) * po / (pa + EPS9);
        }
    }

    // dense score rows: 8 rows x 20 float4 = 160 float4 per warp, coalesced
    float4* basep = (float4*)(out + N * 5) + ((size_t)b * NA + arow) * (NC / 4);
#pragma unroll
    for (int r = 0; r < 5; r++) {
        int idx = r * 32 + lane;              // 0..159
        int row = idx / (NC / 4);             // 0..7 (source lane)
        int k   = idx - row * (NC / 4);
        float nv = __shfl_sync(0xffffffffu, norm, row);
        int   lb = __shfl_sync(0xffffffffu, lbl,  row);
        if (arow + row < NA) {
            float4 w4 = make_float4(0.f, 0.f, 0.f, 0.f);
            if ((lb >> 2) == k) {
                int l4 = lb & 3;
                if      (l4 == 0) w4.x = nv;
                else if (l4 == 1) w4.y = nv;
                else if (l4 == 2) w4.z = nv;
                else              w4.w = nv;
            }
            basep[idx] = w4;
        }
    }
}

// ---------------- launcher ----------------
extern "C" void kernel_launch(void* const* d_in, const int* in_sizes, int n_in,
                              void* d_out, int out_size)
{
    const float* pd_scores = (const float*)d_in[0];
    const float* pd_bboxes = (const float*)d_in[1];
    const float* anc       = (const float*)d_in[2];
    const int*   gt_labels = (const int*)  d_in[3];
    const float* gt_bboxes = (const float*)d_in[4];
    float* out = (float*)d_out;

    (void)in_sizes; (void)n_in; (void)out_size;

    k_bin<<<1, 1024>>>(anc);

    k_phaseA<<<BSZ * NM, 128>>>(pd_scores, pd_bboxes, anc, gt_labels, gt_bboxes);

    dim3 gB((NA + 511) / 512, BSZ);
    k_phaseB<<<gB, 256>>>(pd_scores, pd_bboxes, anc, gt_labels, gt_bboxes);

    dim3 gC((NA + 63) / 64, BSZ);
    k_phaseC<<<gC, 256>>>(gt_bboxes, out);
}

// round 11
// speedup vs baseline: 1.7681x; 1.0425x over previous
#include <cuda_runtime.h>
#include <math.h>
#include <stdint.h>

#define BSZ 16
#define NA  8400
#define NM  64
#define NC  80
#define KTOP 10
#define EPS9 1e-9f

#define NBX   32
#define NBINS 1024         // 32x32 bins of 20px over 640x640
#define INV_BINW 0.05f     // 1/20
#define MAXC  512          // max inside-candidates per gt (exp<=345, 4sigma safe)

#define ATHR 256           // phaseA threads

// ---------------- scratch (__device__ globals; zero-initialized) ----------
__device__ int      g_cnt[BSZ * NA];     // zero at entry (initial + phaseB clean)
__device__ int      g_m[BSZ * NA];
__device__ float    g_al[BSZ * NA];
__device__ float    g_ov[BSZ * NA];
__device__ int      g_lbl[BSZ * NA];     // final label, -1 = background
__device__ int      g_tgt[BSZ * NA];
__device__ float    g_fin[BSZ * NA];
__device__ unsigned g_pos_al[BSZ * NM];  // zeroed by phaseA block bm each launch
__device__ unsigned g_pos_ov[BSZ * NM];
// binning
__device__ float2   g_bxy[NA];
__device__ int      g_bidx[NA];
__device__ int      g_bs[NBINS + 1];

// ---------------- helpers ----------------
static __device__ __forceinline__ float ciou_f(float4 g, float4 p) {
    const float eps = 1e-7f;
    float w1 = g.z - g.x, h1 = g.w - g.y;
    float w2 = p.z - p.x, h2 = p.w - p.y;
    float iw = fmaxf(fminf(g.z, p.z) - fmaxf(g.x, p.x), 0.0f);
    float ih = fmaxf(fminf(g.w, p.w) - fmaxf(g.y, p.y), 0.0f);
    float inter = iw * ih;
    float uni = w1 * h1 + w2 * h2 - inter + eps;
    float iou = inter / uni;
    float cw = fmaxf(g.z, p.z) - fminf(g.x, p.x);
    float ch = fmaxf(g.w, p.w) - fminf(g.y, p.y);
    float c2 = cw * cw + ch * ch + eps;
    float dx = p.x + p.z - g.x - g.z;
    float dy = p.y + p.w - g.y - g.w;
    float rho2 = (dx * dx + dy * dy) * 0.25f;
    float d = atanf(w1 / (h1 + eps)) - atanf(w2 / (h2 + eps));
    float v = 0.4052847345693511f * d * d;   // 4/pi^2
    float alpha = v / (v - iou + 1.0f + eps);
    return iou - (rho2 / c2 + v * alpha);
}

static __device__ __forceinline__ bool inside_box(float2 a, float4 g) {
    float m0 = fminf(a.x - g.x, a.y - g.y);
    float m1 = fminf(g.z - a.x, g.w - a.y);
    return fminf(m0, m1) > EPS9;
}

static __device__ __forceinline__ int bin_of(float2 an) {
    int bx = min(max((int)(an.x * INV_BINW), 0), NBX - 1);
    int by = min(max((int)(an.y * INV_BINW), 0), NBX - 1);
    return by * NBX + bx;
}

// ---------------- K0: bin anchors (single block; 1 thread per bin) --------
__global__ void __launch_bounds__(1024) k_bin(const float* __restrict__ anc) {
    __shared__ int cnt[NBINS];
    __shared__ int ofs[NBINS];
    __shared__ int scn[NBINS];
    int tid = threadIdx.x;
    cnt[tid] = 0;
    __syncthreads();
    for (int a = tid; a < NA; a += 1024) {
        float2 an = __ldg((const float2*)anc + a);
        atomicAdd(&cnt[bin_of(an)], 1);
    }
    __syncthreads();
    int x = cnt[tid];
    scn[tid] = x;
    __syncthreads();
#pragma unroll
    for (int d = 1; d < NBINS; d <<= 1) {
        int v = (tid >= d) ? scn[tid - d] : 0;
        __syncthreads();
        scn[tid] += v;
        __syncthreads();
    }
    int excl = scn[tid] - x;
    g_bs[tid] = excl;
    ofs[tid]  = excl;
    if (tid == 0) g_bs[NBINS] = NA;
    __syncthreads();
    for (int a = tid; a < NA; a += 1024) {
        float2 an = __ldg((const float2*)anc + a);
        int p = atomicAdd(&ofs[bin_of(an)], 1);
        g_bxy[p]  = an;
        g_bidx[p] = a;
    }
}

// ---------------- K1: per (b,m) binned scan + parallel rank top-10 --------
__global__ void __launch_bounds__(ATHR) k_phaseA(
    const float* __restrict__ pd_scores, const float* __restrict__ pd_bboxes,
    const float* __restrict__ anc, const int* __restrict__ gt_labels,
    const float* __restrict__ gt_bboxes)
{
    int bm = blockIdx.x;
    int b = bm >> 6;
    int tid = threadIdx.x;

    __shared__ unsigned long long s_key[MAXC];  // (vbits<<32)|(0x7FFFFFFF - idx)
    __shared__ float s_ovs[MAXC];
    __shared__ int   s_ia[MAXC];
    __shared__ int   s_n;
    if (tid == 0) {
        s_n = 0;
        g_pos_al[bm] = 0u;          // safe: prior replay's phaseC already read
        g_pos_ov[bm] = 0u;
    }

    float4 g = __ldg((const float4*)gt_bboxes + bm);
    int lbl = __ldg(gt_labels + bm);
    const float* sc = pd_scores + (size_t)b * NA * NC + lbl;
    const float4* pb = (const float4*)pd_bboxes + (size_t)b * NA;
    __syncthreads();

    int bx0 = min(max((int)(g.x * INV_BINW), 0), NBX - 1);
    int bx1 = min(max((int)(g.z * INV_BINW), 0), NBX - 1);
    int by0 = min(max((int)(g.y * INV_BINW), 0), NBX - 1);
    int by1 = min(max((int)(g.w * INV_BINW), 0), NBX - 1);

    for (int by = by0; by <= by1; by++) {
        int j0 = g_bs[by * NBX + bx0];
        int j1 = g_bs[by * NBX + bx1 + 1];
        for (int j = j0 + tid; j < j1; j += ATHR) {
            float2 an = g_bxy[j];
            if (!inside_box(an, g)) continue;
            int a = g_bidx[j];
            float4 p = __ldg(pb + a);
            float ov = fmaxf(ciou_f(g, p), 0.0f);
            if (ov <= 0.0f) continue;
            float s = __ldg(sc + (size_t)a * NC);
            float o2 = ov * ov;
            float v = sqrtf(s) * o2 * o2 * o2;   // > 0
            int pos = atomicAdd(&s_n, 1);
            if (pos < MAXC) {
                s_key[pos] = ((unsigned long long)__float_as_uint(v) << 32) |
                             (unsigned)(0x7FFFFFFF - a);
                s_ovs[pos] = ov;
                s_ia[pos]  = a;
            }
        }
    }
    __syncthreads();

    int n = min(s_n, MAXC);

    // parallel rank-select: keys distinct, winner iff rank < KTOP
    for (int c = tid; c < n; c += ATHR) {
        unsigned long long key = s_key[c];
        int rank = 0;
        for (int j = 0; j < n; j++) rank += (s_key[j] > key);
        if (rank < KTOP) {
            int a = s_ia[c];
            size_t i = (size_t)b * NA + a;
            atomicAdd(&g_cnt[i], 1);
            g_m[i]  = bm & 63;
            g_al[i] = __uint_as_float((unsigned)(key >> 32));
            g_ov[i] = s_ovs[c];
        }
    }

    // fillers when n < KTOP: smallest global anchor indices not positive
    if (n < KTOP && tid < n + KTOP) {
        bool inPos = false; int less = 0;
        for (int j = 0; j < n; j++) {
            int ia = s_ia[j];
            inPos |= (ia == tid);
            less  += (ia < tid);
        }
        if (!inPos && (tid - less) < (KTOP - n)) {
            float2 an = __ldg((const float2*)anc + tid);
            if (inside_box(an, g)) {
                size_t i = (size_t)b * NA + tid;
                atomicAdd(&g_cnt[i], 1);
                g_m[i]  = bm & 63;
                g_al[i] = 0.0f;
                float4 p = __ldg(pb + tid);
                g_ov[i] = fmaxf(ciou_f(g, p), 0.0f);
            }
        }
    }
}

// ---------------- K2: resolve assignment + pos-max atomics ----------------
__global__ void __launch_bounds__(256) k_phaseB(
    const float* __restrict__ pd_scores, const float* __restrict__ pd_bboxes,
    const float* __restrict__ anc, const int* __restrict__ gt_labels,
    const float* __restrict__ gt_bboxes)
{
    int b = blockIdx.y;
    int a = blockIdx.x * 256 + threadIdx.x;
    if (a >= NA) return;
    size_t i = (size_t)b * NA + a;

    // independent upfront loads
    int   cnt = __ldg(&g_cnt[i]);
    int   tgt = __ldg(&g_m[i]);
    float al  = __ldg(&g_al[i]);
    float ov  = __ldg(&g_ov[i]);
    g_cnt[i] = 0;                           // self-clean for next launch

    if (cnt == 0) { g_lbl[i] = -1; g_tgt[i] = 0; g_fin[i] = 0.0f; return; }

    if (cnt > 1) {
        // multi-assigned: argmax over m of overlaps (ties -> lowest m)
        float2 an = __ldg((const float2*)anc + a);
        float4 p  = __ldg((const float4*)pd_bboxes + (size_t)b * NA + a);
        const float4* gb = (const float4*)gt_bboxes + b * NM;
        float best = -1.0f; int bmx = 0;
#pragma unroll 4
        for (int m = 0; m < NM; m++) {
            float4 gg = __ldg(gb + m);
            float ovm = inside_box(an, gg) ? fmaxf(ciou_f(gg, p), 0.0f) : 0.0f;
            if (ovm > best) { best = ovm; bmx = m; }
        }
        tgt = bmx; ov = best;
        float4 gg = __ldg(gb + tgt);
        if (inside_box(an, gg) && ov > 0.0f) {
            int lb = __ldg(gt_labels + b * NM + tgt);
            float s = pd_scores[(size_t)b * NA * NC + (size_t)a * NC + lb];
            float o2 = ov * ov;
            al = sqrtf(s) * o2 * o2 * o2;
        } else {
            al = 0.0f;
        }
    }

    g_lbl[i] = __ldg(gt_labels + b * NM + tgt);
    g_tgt[i] = tgt;
    g_fin[i] = al;
    atomicMax(&g_pos_al[b * NM + tgt], __float_as_uint(al));
    atomicMax(&g_pos_ov[b * NM + tgt], __float_as_uint(ov));
}

// ---------------- K3: all outputs (warp-autonomous, shfl exchange) --------
__global__ void __launch_bounds__(256) k_phaseC(
    const float* __restrict__ gt_bboxes, float* __restrict__ out)
{
    int b    = blockIdx.y;
    int lane = threadIdx.x & 31;
    int w    = threadIdx.x >> 5;
    int arow = blockIdx.x * 64 + w * 8;      // this warp's 8 anchors

    const size_t N = (size_t)BSZ * NA;

    float norm = 0.0f; int lbl = -1;
    int a = arow + lane;
    if (lane < 8 && a < NA) {
        size_t i = (size_t)b * NA + a;
        lbl     = __ldg(&g_lbl[i]);
        int tgt = __ldg(&g_tgt[i]);
        int fg  = lbl >= 0;

        float4 box = __ldg((const float4*)gt_bboxes + b * NM + tgt);
        out[i] = fg ? (float)lbl : (float)NC;               // labels
        ((float4*)(out + N))[i] = box;                      // bboxes
        out[N * (size_t)85 + i] = fg ? 1.0f : 0.0f;         // fg
        out[N * (size_t)86 + i] = (float)tgt;               // gt_idx

        if (fg) {
            float pa = __uint_as_float(__ldg(&g_pos_al[b * NM + tgt]));
            float po = __uint_as_float(__ldg(&g_pos_ov[b * NM + tgt]));
            norm = __ldg(&g_fin[i]) * po / (pa + EPS9);
        }
    }

    // dense score rows: 8 rows x 20 float4 = 160 float4 per warp, coalesced
    float4* basep = (float4*)(out + N * 5) + ((size_t)b * NA + arow) * (NC / 4);
#pragma unroll
    for (int r = 0; r < 5; r++) {
        int idx = r * 32 + lane;              // 0..159
        int row = idx / (NC / 4);             // 0..7 (source lane)
        int k   = idx - row * (NC / 4);
        float nv = __shfl_sync(0xffffffffu, norm, row);
        int   lb = __shfl_sync(0xffffffffu, lbl,  row);
        if (arow + row < NA) {
            float4 w4 = make_float4(0.f, 0.f, 0.f, 0.f);
            if ((lb >> 2) == k) {
                int l4 = lb & 3;
                if      (l4 == 0) w4.x = nv;
                else if (l4 == 1) w4.y = nv;
                else if (l4 == 2) w4.z = nv;
                else              w4.w = nv;
            }
            basep[idx] = w4;
        }
    }
}

// ---------------- launcher ----------------
extern "C" void kernel_launch(void* const* d_in, const int* in_sizes, int n_in,
                              void* d_out, int out_size)
{
    const float* pd_scores = (const float*)d_in[0];
    const float* pd_bboxes = (const float*)d_in[1];
    const float* anc       = (const float*)d_in[2];
    const int*   gt_labels = (const int*)  d_in[3];
    const float* gt_bboxes = (const float*)d_in[4];
    float* out = (float*)d_out;

    (void)in_sizes; (void)n_in; (void)out_size;

    k_bin<<<1, 1024>>>(anc);

    k_phaseA<<<BSZ * NM, ATHR>>>(pd_scores, pd_bboxes, anc, gt_labels, gt_bboxes);

    dim3 gB((NA + 255) / 256, BSZ);
    k_phaseB<<<gB, 256>>>(pd_scores, pd_bboxes, anc, gt_labels, gt_bboxes);

    dim3 gC((NA + 63) / 64, BSZ);
    k_phaseC<<<gC, 256>>>(gt_bboxes, out);
}